// round 9
// baseline (speedup 1.0000x reference)
#include <cuda_runtime.h>
#include <cuda_bf16.h>
#include <cstdint>

#define NN 4096
#define DD 128
#define TILE 128

// ---------------------------------------------------------------- scratch
__device__ __nv_bfloat16 g_E[(size_t)NN * NN];           // 32 MB e_ij
__device__ __nv_bfloat16 g_Xb[(size_t)NN * DD];          // bf16 copies of inputs
__device__ __nv_bfloat16 g_Yb[(size_t)NN * DD];
__device__ float  g_p[NN], g_P[NN], g_yn[NN], g_xn[NN], g_Row[NN];
__device__ double g_acc[8];
// g_acc: [0]=Sp  [1]=SP  [2]=S_all  [3]=SlogE  [4]=SlogM  [5]=SsigPos  [6]=SsigNeg

// ---------------------------------------------------------------- zero
__global__ void kZero() {
    int t = threadIdx.x;
    for (int i = t; i < NN; i += 256) g_Row[i] = 0.f;
    if (t < 8) g_acc[t] = 0.0;
}

// ---------------------------------------------------------------- diag + norms + bf16 convert
__global__ void kDiag(const float* __restrict__ X, const float* __restrict__ Y) {
    int warp = (blockIdx.x * blockDim.x + threadIdx.x) >> 5;
    int lane = threadIdx.x & 31;
    __shared__ double s_p[8], s_P[8];
    if (warp < NN) {
        const float4* x4 = (const float4*)(X + (size_t)warp * DD);
        const float4* y4 = (const float4*)(Y + (size_t)warp * DD);
        float4 xv = x4[lane];
        float4 yv = y4[lane];
        {
            __nv_bfloat162 a = __float22bfloat162_rn(make_float2(xv.x, xv.y));
            __nv_bfloat162 b = __float22bfloat162_rn(make_float2(xv.z, xv.w));
            *(uint2*)(&g_Xb[(size_t)warp * DD + lane * 4]) =
                make_uint2(*(unsigned*)&a, *(unsigned*)&b);
            __nv_bfloat162 c = __float22bfloat162_rn(make_float2(yv.x, yv.y));
            __nv_bfloat162 d = __float22bfloat162_rn(make_float2(yv.z, yv.w));
            *(uint2*)(&g_Yb[(size_t)warp * DD + lane * 4]) =
                make_uint2(*(unsigned*)&c, *(unsigned*)&d);
        }
        float xn = xv.x * xv.x + xv.y * xv.y + xv.z * xv.z + xv.w * xv.w;
        float yn = yv.x * yv.x + yv.y * yv.y + yv.z * yv.z + yv.w * yv.w;
        float cr = xv.x * yv.x + xv.y * yv.y + xv.z * yv.z + xv.w * yv.w;
        for (int o = 16; o > 0; o >>= 1) {
            xn += __shfl_xor_sync(0xffffffffu, xn, o);
            yn += __shfl_xor_sync(0xffffffffu, yn, o);
            cr += __shfl_xor_sync(0xffffffffu, cr, o);
        }
        if (lane == 0) {
            float sq = fmaxf(yn + xn - 2.f * cr, 0.f);
            float p  = 1.f / (1.f + sq);
            float P  = -__logf(1.f + sq);
            g_p[warp]  = p;
            g_P[warp]  = P;
            g_yn[warp] = yn;
            g_xn[warp] = xn;
            int w = threadIdx.x >> 5;
            s_p[w] = (double)p;
            s_P[w] = (double)P;
        }
    }
    __syncthreads();
    if (threadIdx.x == 0) {
        double sp = 0.0, sP = 0.0;
        for (int w = 0; w < 8; w++) { sp += s_p[w]; sP += s_P[w]; }
        atomicAdd(&g_acc[0], sp);
        atomicAdd(&g_acc[1], sP);
    }
}

// ---------------------------------------------------------------- HMMA GEMM + epilogue
// 128x128 tile per CTA; 8 warps as 2x4 (64x32 each); mma.sync m16n8k16 bf16
// K in two 64-wide smem chunks [128][72] (pad 8 -> conflict-free frag loads)
#define LDK 72
#define LDE 136
__global__ __launch_bounds__(256, 1)
void kGemm() {
    __shared__ __align__(16) char sm[2 * TILE * LDK * 2];   // 36864 B (A|B, reused as E stage)
    __shared__ float ys[TILE], xs[TILE], ps[TILE];
    __shared__ float red[3][8];

    __nv_bfloat16* smA = (__nv_bfloat16*)sm;                 // [128][72]
    __nv_bfloat16* smB = (__nv_bfloat16*)(sm + TILE * LDK * 2);
    __nv_bfloat16* smE = (__nv_bfloat16*)sm;                 // [128][136] staging (reuse)

    const int t    = threadIdx.x;
    const int wid  = t >> 5;
    const int lane = t & 31;
    const int g    = lane >> 2;
    const int t4   = lane & 3;
    const int wm   = wid >> 2;       // 0..1  -> 64-row half
    const int wn   = wid & 3;        // 0..3  -> 32-col quarter
    const int m0 = blockIdx.y * TILE;
    const int n0 = blockIdx.x * TILE;

    if (t < 128) { ys[t] = g_yn[m0 + t]; ps[t] = g_p[m0 + t]; }
    else         { xs[t - 128] = g_xn[n0 + (t - 128)]; }

    float acc[4][4][4];
#pragma unroll
    for (int m = 0; m < 4; m++)
#pragma unroll
        for (int n = 0; n < 4; n++)
#pragma unroll
            for (int r = 0; r < 4; r++) acc[m][n][r] = 0.f;

#pragma unroll 1
    for (int kc = 0; kc < 2; kc++) {
        // load K-chunk: 128 rows x 64 bf16 each for A (Y) and B (X)
        for (int i = t; i < 1024; i += 256) {
            int row = i >> 3;
            int c8  = (i & 7) * 8;
            *(uint4*)&smA[row * LDK + c8] =
                *(const uint4*)&g_Yb[(size_t)(m0 + row) * DD + kc * 64 + c8];
            *(uint4*)&smB[row * LDK + c8] =
                *(const uint4*)&g_Xb[(size_t)(n0 + row) * DD + kc * 64 + c8];
        }
        __syncthreads();

#pragma unroll
        for (int ks = 0; ks < 4; ks++) {
            const int kb = ks * 16;
            uint32_t bb[4][2];
#pragma unroll
            for (int n = 0; n < 4; n++) {
                int br = wn * 32 + n * 8 + g;
                bb[n][0] = *(const uint32_t*)&smB[br * LDK + kb + 2 * t4];
                bb[n][1] = *(const uint32_t*)&smB[br * LDK + kb + 8 + 2 * t4];
            }
#pragma unroll
            for (int m = 0; m < 4; m++) {
                int ar = wm * 64 + m * 16 + g;
                uint32_t a0 = *(const uint32_t*)&smA[ar * LDK + kb + 2 * t4];
                uint32_t a1 = *(const uint32_t*)&smA[(ar + 8) * LDK + kb + 2 * t4];
                uint32_t a2 = *(const uint32_t*)&smA[ar * LDK + kb + 8 + 2 * t4];
                uint32_t a3 = *(const uint32_t*)&smA[(ar + 8) * LDK + kb + 8 + 2 * t4];
#pragma unroll
                for (int n = 0; n < 4; n++) {
                    asm volatile(
                        "mma.sync.aligned.m16n8k16.row.col.f32.bf16.bf16.f32 "
                        "{%0,%1,%2,%3}, {%4,%5,%6,%7}, {%8,%9}, {%0,%1,%2,%3};"
                        : "+f"(acc[m][n][0]), "+f"(acc[m][n][1]),
                          "+f"(acc[m][n][2]), "+f"(acc[m][n][3])
                        : "r"(a0), "r"(a1), "r"(a2), "r"(a3),
                          "r"(bb[n][0]), "r"(bb[n][1]));
                }
            }
        }
        __syncthreads();
    }

    // ------- epilogue: e = 1/(1+sq), stats, stage bf16 e in smem -------
    float se = 0.f, slE = 0.f, slM = 0.f;
#pragma unroll
    for (int m = 0; m < 4; m++) {
#pragma unroll
        for (int rr = 0; rr < 2; rr++) {
            const int rloc = wm * 64 + m * 16 + rr * 8 + g;
            const float yni = ys[rloc];
            const float pmi = ps[rloc];
            float er = 0.f;
#pragma unroll
            for (int n = 0; n < 4; n++) {
                const int cloc = wn * 32 + n * 8 + 2 * t4;
                float d0 = acc[m][n][rr * 2 + 0];
                float d1 = acc[m][n][rr * 2 + 1];
                float sq0 = fmaxf(yni + xs[cloc]     - 2.f * d0, 0.f);
                float sq1 = fmaxf(yni + xs[cloc + 1] - 2.f * d1, 0.f);
                float op0 = 1.f + sq0, op1 = 1.f + sq1;
                float e0 = __fdividef(1.f, op0);
                float e1 = __fdividef(1.f, op1);
                se  += e0 + e1;
                er  += e0 + e1;
                slE -= __logf(op0) + __logf(op1);
                slM += __logf(0.5f * (pmi + e0)) + __logf(0.5f * (pmi + e1));
                __nv_bfloat162 pb = __float22bfloat162_rn(make_float2(e0, e1));
                *(uint32_t*)&smE[rloc * LDE + cloc] = *(unsigned*)&pb;
            }
            // reduce row sum over the 4 lanes sharing this row (t4 group)
            er += __shfl_xor_sync(0xffffffffu, er, 1);
            er += __shfl_xor_sync(0xffffffffu, er, 2);
            if (t4 == 0) atomicAdd(&g_Row[m0 + rloc], er);
        }
    }

    // block reduce the 3 scalars
    for (int o = 16; o > 0; o >>= 1) {
        se  += __shfl_xor_sync(0xffffffffu, se, o);
        slE += __shfl_xor_sync(0xffffffffu, slE, o);
        slM += __shfl_xor_sync(0xffffffffu, slM, o);
    }
    if (lane == 0) { red[0][wid] = se; red[1][wid] = slE; red[2][wid] = slM; }
    __syncthreads();
    if (t == 0) {
        double a0 = 0, a1 = 0, a2 = 0;
        for (int k = 0; k < 8; k++) { a0 += red[0][k]; a1 += red[1][k]; a2 += red[2][k]; }
        atomicAdd(&g_acc[2], a0);
        atomicAdd(&g_acc[3], a1);
        atomicAdd(&g_acc[4], a2);
    }

    // coalesced store of staged e tile: 128 rows x 16 chunks of 8 bf16 (uint4)
    for (int i = t; i < 2048; i += 256) {
        int row = i >> 4;
        int c8  = (i & 15) * 8;
        *(uint4*)&g_E[(size_t)(m0 + row) * NN + n0 + c8] =
            *(const uint4*)&smE[row * LDE + c8];
    }
}

// ---------------------------------------------------------------- sigmoid pass
#define SIG_BLOCKS 1184
__global__ __launch_bounds__(256, 8) void kSig() {
    double Sp    = g_acc[0];
    double S_all = g_acc[2];
    double S_N   = S_all - Sp;
    double S_M   = 0.5 * ((double)(NN - 1) * Sp + S_N);
    const double cnt = (double)NN * (double)(NN - 1);
    float C = (float)((S_M / cnt) * (S_N / cnt));

    const size_t nvec   = (size_t)NN * NN / 8;
    const size_t stride = (size_t)SIG_BLOCKS * 256;
    size_t tid = (size_t)blockIdx.x * 256 + threadIdx.x;

    float sp = 0.f, sn = 0.f;
    for (size_t i = tid; i < nvec; i += stride) {
        int m = (int)((i * 8) >> 12);
        float pm = __ldg(&g_p[m]);
        uint4 raw = __ldg((const uint4*)&g_E[i * 8]);
        float2 f;
        float e;
#define SIG_TERM(E) { e = (E); float u = 0.5f * pm * (pm + e), v = 0.5f * (pm + e) * e; \
                      sp += __fdividef(u, u + C); sn += __fdividef(v, v + C); }
        f = __bfloat1622float2(*(__nv_bfloat162*)&raw.x); SIG_TERM(f.x); SIG_TERM(f.y);
        f = __bfloat1622float2(*(__nv_bfloat162*)&raw.y); SIG_TERM(f.x); SIG_TERM(f.y);
        f = __bfloat1622float2(*(__nv_bfloat162*)&raw.z); SIG_TERM(f.x); SIG_TERM(f.y);
        f = __bfloat1622float2(*(__nv_bfloat162*)&raw.w); SIG_TERM(f.x); SIG_TERM(f.y);
#undef SIG_TERM
    }
    for (int o = 16; o > 0; o >>= 1) {
        sp += __shfl_xor_sync(0xffffffffu, sp, o);
        sn += __shfl_xor_sync(0xffffffffu, sn, o);
    }
    __shared__ double rp[8], rn_[8];
    int w = threadIdx.x >> 5;
    if ((threadIdx.x & 31) == 0) { rp[w] = (double)sp; rn_[w] = (double)sn; }
    __syncthreads();
    if (threadIdx.x == 0) {
        double a = 0, b = 0;
        for (int k = 0; k < 8; k++) { a += rp[k]; b += rn_[k]; }
        atomicAdd(&g_acc[5], a);
        atomicAdd(&g_acc[6], b);
    }
}

// ---------------------------------------------------------------- final
__global__ void kFinal(float* __restrict__ out) {
    __shared__ double s_tp[256], s_d[256];
    int t = threadIdx.x;
    double Sp = g_acc[0], SP = g_acc[1], S_all = g_acc[2];
    double SlogE = g_acc[3], SlogM = g_acc[4], SsP = g_acc[5], SsN = g_acc[6];
    double S_N = S_all - Sp;
    const double cnt = (double)NN * (double)(NN - 1);
    double S_M = 0.5 * ((NN - 1.0) * Sp + S_N);
    double C   = (S_M / cnt) * (S_N / cnt);

    double tp = 0.0, dd = 0.0;
    for (int i = t; i < NN; i += 256) {
        double pm = (double)g_p[i];
        double R  = (double)g_Row[i] - pm;
        double w  = pm * 0.5 * ((NN - 1.0) * pm + R) / (NN - 1.0);
        tp += w / (w + C);
        dd += pm * pm / (pm * pm + C);
    }
    s_tp[t] = tp; s_d[t] = dd;
    __syncthreads();
    for (int o = 128; o > 0; o >>= 1) {
        if (t < o) { s_tp[t] += s_tp[t + o]; s_d[t] += s_d[t + o]; }
        __syncthreads();
    }
    if (t == 0) {
        double TP   = s_tp[0] / NN;
        double dsum = s_d[0];
        double lb0 = log(S_M / cnt), lb1 = log(S_N / cnt), L = lb0 + lb1;
        double meanP = SP / NN;
        double meanM = (SlogM - SP) / cnt;
        double meanN = (SlogE - SP) / cnt;
        double o0 = meanP + meanM - L;
        double o1 = meanM + meanN - L;
        double sigP = (SsP - dsum) / cnt;
        double sigN = (SsN - dsum) / cnt;
        double FP = sigN;
        out[0] = (float)o0;
        out[1] = (float)o1;
        out[2] = (float)sigP;
        out[3] = (float)sigN;
        out[4] = (float)((TP + 1.0 - FP) * 0.5);
        out[5] = (float)TP;
        out[6] = (float)(TP / (TP + FP));
        out[7] = (float)L;
        out[8] = (float)(2.0 - o0);
    }
}

// ---------------------------------------------------------------- launch
extern "C" void kernel_launch(void* const* d_in, const int* in_sizes, int n_in,
                              void* d_out, int out_size) {
    const float* X = (const float*)d_in[0];   // z_x  (columns j)
    const float* Y = (const float*)d_in[1];   // z_y  (rows i)
    kZero<<<1, 256>>>();
    kDiag<<<NN / 8, 256>>>(X, Y);
    kGemm<<<dim3(NN / TILE, NN / TILE), 256>>>();
    kSig<<<SIG_BLOCKS, 256>>>();
    kFinal<<<1, 256>>>((float*)d_out);
}

// round 10
// speedup vs baseline: 1.8326x; 1.8326x over previous
#include <cuda_runtime.h>
#include <cuda_bf16.h>
#include <cstdint>

#define NN 4096
#define DD 128
#define TILE 128

// ---------------------------------------------------------------- scratch
__device__ __nv_bfloat16 g_E[(size_t)NN * NN];           // 32 MB e_ij
__device__ __nv_bfloat16 g_Xb[(size_t)NN * DD];          // bf16 copies of inputs
__device__ __nv_bfloat16 g_Yb[(size_t)NN * DD];
__device__ float  g_p[NN], g_P[NN], g_yn[NN], g_xn[NN], g_Row[NN];
__device__ double g_acc[8];
// g_acc: [0]=Sp  [1]=SP  [2]=S_all  [3]=SlogE  [4]=SlogM  [5]=SsigPos  [6]=SsigNeg

// ---------------------------------------------------------------- zero
__global__ void kZero() {
    int t = threadIdx.x;
    for (int i = t; i < NN; i += 256) g_Row[i] = 0.f;
    if (t < 8) g_acc[t] = 0.0;
}

// ---------------------------------------------------------------- diag + norms + bf16 convert
__global__ void kDiag(const float* __restrict__ X, const float* __restrict__ Y) {
    int warp = (blockIdx.x * blockDim.x + threadIdx.x) >> 5;
    int lane = threadIdx.x & 31;
    __shared__ double s_p[8], s_P[8];
    if (warp < NN) {
        const float4* x4 = (const float4*)(X + (size_t)warp * DD);
        const float4* y4 = (const float4*)(Y + (size_t)warp * DD);
        float4 xv = x4[lane];
        float4 yv = y4[lane];
        {
            __nv_bfloat162 a = __float22bfloat162_rn(make_float2(xv.x, xv.y));
            __nv_bfloat162 b = __float22bfloat162_rn(make_float2(xv.z, xv.w));
            *(uint2*)(&g_Xb[(size_t)warp * DD + lane * 4]) =
                make_uint2(*(unsigned*)&a, *(unsigned*)&b);
            __nv_bfloat162 c = __float22bfloat162_rn(make_float2(yv.x, yv.y));
            __nv_bfloat162 d = __float22bfloat162_rn(make_float2(yv.z, yv.w));
            *(uint2*)(&g_Yb[(size_t)warp * DD + lane * 4]) =
                make_uint2(*(unsigned*)&c, *(unsigned*)&d);
        }
        float xn = xv.x * xv.x + xv.y * xv.y + xv.z * xv.z + xv.w * xv.w;
        float yn = yv.x * yv.x + yv.y * yv.y + yv.z * yv.z + yv.w * yv.w;
        float cr = xv.x * yv.x + xv.y * yv.y + xv.z * yv.z + xv.w * yv.w;
        for (int o = 16; o > 0; o >>= 1) {
            xn += __shfl_xor_sync(0xffffffffu, xn, o);
            yn += __shfl_xor_sync(0xffffffffu, yn, o);
            cr += __shfl_xor_sync(0xffffffffu, cr, o);
        }
        if (lane == 0) {
            float sq = fmaxf(yn + xn - 2.f * cr, 0.f);
            float p  = 1.f / (1.f + sq);
            float P  = -__logf(1.f + sq);
            g_p[warp]  = p;
            g_P[warp]  = P;
            g_yn[warp] = yn;
            g_xn[warp] = xn;
            int w = threadIdx.x >> 5;
            s_p[w] = (double)p;
            s_P[w] = (double)P;
        }
    }
    __syncthreads();
    if (threadIdx.x == 0) {
        double sp = 0.0, sP = 0.0;
        for (int w = 0; w < 8; w++) { sp += s_p[w]; sP += s_P[w]; }
        atomicAdd(&g_acc[0], sp);
        atomicAdd(&g_acc[1], sP);
    }
}

// ---------------------------------------------------------------- HMMA GEMM + epilogue
// 128x128 tile per CTA; 8 warps as 2x4 (64x32 each); mma.sync m16n8k16 bf16
// K in two 64-wide smem chunks [128][72] (pad 8 -> conflict-free frag loads)
#define LDK 72
#define LDE 136
__global__ __launch_bounds__(256, 2)
void kGemm() {
    __shared__ __align__(16) char sm[2 * TILE * LDK * 2];   // 36864 B (A|B, reused as E stage)
    __shared__ float ys[TILE], xs[TILE], ps[TILE];
    __shared__ float red[3][8];

    __nv_bfloat16* smA = (__nv_bfloat16*)sm;                 // [128][72]
    __nv_bfloat16* smB = (__nv_bfloat16*)(sm + TILE * LDK * 2);
    __nv_bfloat16* smE = (__nv_bfloat16*)sm;                 // [128][136] staging (reuse)

    const int t    = threadIdx.x;
    const int wid  = t >> 5;
    const int lane = t & 31;
    const int g    = lane >> 2;
    const int t4   = lane & 3;
    const int wm   = wid >> 2;       // 0..1  -> 64-row half
    const int wn   = wid & 3;        // 0..3  -> 32-col quarter
    const int m0 = blockIdx.y * TILE;
    const int n0 = blockIdx.x * TILE;

    if (t < 128) { ys[t] = g_yn[m0 + t]; ps[t] = g_p[m0 + t]; }
    else         { xs[t - 128] = g_xn[n0 + (t - 128)]; }

    float acc[4][4][4];
#pragma unroll
    for (int m = 0; m < 4; m++)
#pragma unroll
        for (int n = 0; n < 4; n++)
#pragma unroll
            for (int r = 0; r < 4; r++) acc[m][n][r] = 0.f;

#pragma unroll 1
    for (int kc = 0; kc < 2; kc++) {
        // load K-chunk: 128 rows x 64 bf16 each for A (Y) and B (X)
        for (int i = t; i < 1024; i += 256) {
            int row = i >> 3;
            int c8  = (i & 7) * 8;
            *(uint4*)&smA[row * LDK + c8] =
                *(const uint4*)&g_Yb[(size_t)(m0 + row) * DD + kc * 64 + c8];
            *(uint4*)&smB[row * LDK + c8] =
                *(const uint4*)&g_Xb[(size_t)(n0 + row) * DD + kc * 64 + c8];
        }
        __syncthreads();

#pragma unroll
        for (int ks = 0; ks < 4; ks++) {
            const int kb = ks * 16;
            uint32_t bb[4][2];
#pragma unroll
            for (int n = 0; n < 4; n++) {
                int br = wn * 32 + n * 8 + g;
                bb[n][0] = *(const uint32_t*)&smB[br * LDK + kb + 2 * t4];
                bb[n][1] = *(const uint32_t*)&smB[br * LDK + kb + 8 + 2 * t4];
            }
#pragma unroll
            for (int m = 0; m < 4; m++) {
                int ar = wm * 64 + m * 16 + g;
                uint32_t a0 = *(const uint32_t*)&smA[ar * LDK + kb + 2 * t4];
                uint32_t a1 = *(const uint32_t*)&smA[(ar + 8) * LDK + kb + 2 * t4];
                uint32_t a2 = *(const uint32_t*)&smA[ar * LDK + kb + 8 + 2 * t4];
                uint32_t a3 = *(const uint32_t*)&smA[(ar + 8) * LDK + kb + 8 + 2 * t4];
#pragma unroll
                for (int n = 0; n < 4; n++) {
                    asm volatile(
                        "mma.sync.aligned.m16n8k16.row.col.f32.bf16.bf16.f32 "
                        "{%0,%1,%2,%3}, {%4,%5,%6,%7}, {%8,%9}, {%0,%1,%2,%3};"
                        : "+f"(acc[m][n][0]), "+f"(acc[m][n][1]),
                          "+f"(acc[m][n][2]), "+f"(acc[m][n][3])
                        : "r"(a0), "r"(a1), "r"(a2), "r"(a3),
                          "r"(bb[n][0]), "r"(bb[n][1]));
                }
            }
        }
        __syncthreads();
    }

    // ------- epilogue: e = 1/(1+sq), stats, stage bf16 e in smem -------
    // logs fused: sum(log a_i) over 4 elems -> log(prod a_i); fp32-range safe
    float se = 0.f, slE = 0.f, slM = 0.f;
#pragma unroll
    for (int m = 0; m < 4; m++) {
#pragma unroll
        for (int rr = 0; rr < 2; rr++) {
            const int rloc = wm * 64 + m * 16 + rr * 8 + g;
            const float yni = ys[rloc];
            const float pmi = ps[rloc];
            float er = 0.f;
#pragma unroll
            for (int nh = 0; nh < 2; nh++) {       // two n-pairs of 2 -> 4 elems each
                float prE = 1.f, prM = 1.f;
#pragma unroll
                for (int np = 0; np < 2; np++) {
                    const int n = nh * 2 + np;
                    const int cloc = wn * 32 + n * 8 + 2 * t4;
                    float d0 = acc[m][n][rr * 2 + 0];
                    float d1 = acc[m][n][rr * 2 + 1];
                    float sq0 = fmaxf(yni + xs[cloc]     - 2.f * d0, 0.f);
                    float sq1 = fmaxf(yni + xs[cloc + 1] - 2.f * d1, 0.f);
                    float op0 = 1.f + sq0, op1 = 1.f + sq1;
                    float e0 = __fdividef(1.f, op0);
                    float e1 = __fdividef(1.f, op1);
                    se  += e0 + e1;
                    er  += e0 + e1;
                    prE *= op0 * op1;
                    prM *= (0.5f * (pmi + e0)) * (0.5f * (pmi + e1));
                    __nv_bfloat162 pb = __float22bfloat162_rn(make_float2(e0, e1));
                    *(uint32_t*)&smE[rloc * LDE + cloc] = *(unsigned*)&pb;
                }
                slE -= __logf(prE);
                slM += __logf(prM);
            }
            // reduce row sum over the 4 lanes sharing this row (t4 group)
            er += __shfl_xor_sync(0xffffffffu, er, 1);
            er += __shfl_xor_sync(0xffffffffu, er, 2);
            if (t4 == 0) atomicAdd(&g_Row[m0 + rloc], er);
        }
    }

    // block reduce the 3 scalars
    for (int o = 16; o > 0; o >>= 1) {
        se  += __shfl_xor_sync(0xffffffffu, se, o);
        slE += __shfl_xor_sync(0xffffffffu, slE, o);
        slM += __shfl_xor_sync(0xffffffffu, slM, o);
    }
    if (lane == 0) { red[0][wid] = se; red[1][wid] = slE; red[2][wid] = slM; }
    __syncthreads();
    if (t == 0) {
        double a0 = 0, a1 = 0, a2 = 0;
        for (int k = 0; k < 8; k++) { a0 += red[0][k]; a1 += red[1][k]; a2 += red[2][k]; }
        atomicAdd(&g_acc[2], a0);
        atomicAdd(&g_acc[3], a1);
        atomicAdd(&g_acc[4], a2);
    }

    // coalesced store of staged e tile: 128 rows x 16 chunks of 8 bf16 (uint4)
    for (int i = t; i < 2048; i += 256) {
        int row = i >> 4;
        int c8  = (i & 15) * 8;
        *(uint4*)&g_E[(size_t)(m0 + row) * NN + n0 + c8] =
            *(const uint4*)&smE[row * LDE + c8];
    }
}

// ---------------------------------------------------------------- sigmoid pass
#define SIG_BLOCKS 1184
__global__ __launch_bounds__(256, 8) void kSig() {
    double Sp    = g_acc[0];
    double S_all = g_acc[2];
    double S_N   = S_all - Sp;
    double S_M   = 0.5 * ((double)(NN - 1) * Sp + S_N);
    const double cnt = (double)NN * (double)(NN - 1);
    float C = (float)((S_M / cnt) * (S_N / cnt));

    const size_t nvec   = (size_t)NN * NN / 8;
    const size_t stride = (size_t)SIG_BLOCKS * 256;
    size_t tid = (size_t)blockIdx.x * 256 + threadIdx.x;

    float sp = 0.f, sn = 0.f;
    for (size_t i = tid; i < nvec; i += stride) {
        int m = (int)((i * 8) >> 12);
        float pm = __ldg(&g_p[m]);
        uint4 raw = __ldg((const uint4*)&g_E[i * 8]);
        float2 f;
        float e;
#define SIG_TERM(E) { e = (E); float u = 0.5f * pm * (pm + e), v = 0.5f * (pm + e) * e; \
                      sp += __fdividef(u, u + C); sn += __fdividef(v, v + C); }
        f = __bfloat1622float2(*(__nv_bfloat162*)&raw.x); SIG_TERM(f.x); SIG_TERM(f.y);
        f = __bfloat1622float2(*(__nv_bfloat162*)&raw.y); SIG_TERM(f.x); SIG_TERM(f.y);
        f = __bfloat1622float2(*(__nv_bfloat162*)&raw.z); SIG_TERM(f.x); SIG_TERM(f.y);
        f = __bfloat1622float2(*(__nv_bfloat162*)&raw.w); SIG_TERM(f.x); SIG_TERM(f.y);
#undef SIG_TERM
    }
    for (int o = 16; o > 0; o >>= 1) {
        sp += __shfl_xor_sync(0xffffffffu, sp, o);
        sn += __shfl_xor_sync(0xffffffffu, sn, o);
    }
    __shared__ double rp[8], rn_[8];
    int w = threadIdx.x >> 5;
    if ((threadIdx.x & 31) == 0) { rp[w] = (double)sp; rn_[w] = (double)sn; }
    __syncthreads();
    if (threadIdx.x == 0) {
        double a = 0, b = 0;
        for (int k = 0; k < 8; k++) { a += rp[k]; b += rn_[k]; }
        atomicAdd(&g_acc[5], a);
        atomicAdd(&g_acc[6], b);
    }
}

// ---------------------------------------------------------------- final
__global__ void kFinal(float* __restrict__ out) {
    __shared__ double s_tp[256], s_d[256];
    int t = threadIdx.x;
    double Sp = g_acc[0], SP = g_acc[1], S_all = g_acc[2];
    double SlogE = g_acc[3], SlogM = g_acc[4], SsP = g_acc[5], SsN = g_acc[6];
    double S_N = S_all - Sp;
    const double cnt = (double)NN * (double)(NN - 1);
    double S_M = 0.5 * ((NN - 1.0) * Sp + S_N);
    double C   = (S_M / cnt) * (S_N / cnt);

    double tp = 0.0, dd = 0.0;
    for (int i = t; i < NN; i += 256) {
        double pm = (double)g_p[i];
        double R  = (double)g_Row[i] - pm;
        double w  = pm * 0.5 * ((NN - 1.0) * pm + R) / (NN - 1.0);
        tp += w / (w + C);
        dd += pm * pm / (pm * pm + C);
    }
    s_tp[t] = tp; s_d[t] = dd;
    __syncthreads();
    for (int o = 128; o > 0; o >>= 1) {
        if (t < o) { s_tp[t] += s_tp[t + o]; s_d[t] += s_d[t + o]; }
        __syncthreads();
    }
    if (t == 0) {
        double TP   = s_tp[0] / NN;
        double dsum = s_d[0];
        double lb0 = log(S_M / cnt), lb1 = log(S_N / cnt), L = lb0 + lb1;
        double meanP = SP / NN;
        double meanM = (SlogM - SP) / cnt;
        double meanN = (SlogE - SP) / cnt;
        double o0 = meanP + meanM - L;
        double o1 = meanM + meanN - L;
        double sigP = (SsP - dsum) / cnt;
        double sigN = (SsN - dsum) / cnt;
        double FP = sigN;
        out[0] = (float)o0;
        out[1] = (float)o1;
        out[2] = (float)sigP;
        out[3] = (float)sigN;
        out[4] = (float)((TP + 1.0 - FP) * 0.5);
        out[5] = (float)TP;
        out[6] = (float)(TP / (TP + FP));
        out[7] = (float)L;
        out[8] = (float)(2.0 - o0);
    }
}

// ---------------------------------------------------------------- launch
extern "C" void kernel_launch(void* const* d_in, const int* in_sizes, int n_in,
                              void* d_out, int out_size) {
    const float* X = (const float*)d_in[0];   // z_x  (columns j)
    const float* Y = (const float*)d_in[1];   // z_y  (rows i)
    kZero<<<1, 256>>>();
    kDiag<<<NN / 8, 256>>>(X, Y);
    kGemm<<<dim3(NN / TILE, NN / TILE), 256>>>();
    kSig<<<SIG_BLOCKS, 256>>>();
    kFinal<<<1, 256>>>((float*)d_out);
}

// round 12
// speedup vs baseline: 1.8331x; 1.0003x over previous
#include <cuda_runtime.h>
#include <cuda_bf16.h>
#include <cstdint>

#define NN 4096
#define DD 128
#define TILE 128

// ---------------------------------------------------------------- scratch
__device__ __nv_bfloat16 g_E[(size_t)NN * NN];           // 32 MB e_ij
__device__ __nv_bfloat16 g_Xb[(size_t)NN * DD];          // bf16 copies of inputs
__device__ __nv_bfloat16 g_Yb[(size_t)NN * DD];
__device__ float  g_p[NN], g_P[NN], g_yn[NN], g_xn[NN], g_Row[NN];
__device__ double g_acc[8];
// g_acc: [0]=Sp  [1]=SP  [2]=S_all  [3]=SlogE  [4]=SlogM  [5]=SsigPos  [6]=SsigNeg
// NOTE: g_acc and g_Row are zero at module load and re-zeroed at the END of
// kFinal each run, so every replay starts clean (graph-deterministic).

// ---------------------------------------------------------------- diag + norms + bf16 convert
__global__ void kDiag(const float* __restrict__ X, const float* __restrict__ Y) {
    int warp = (blockIdx.x * blockDim.x + threadIdx.x) >> 5;
    int lane = threadIdx.x & 31;
    __shared__ double s_p[8], s_P[8];
    if (warp < NN) {
        const float4* x4 = (const float4*)(X + (size_t)warp * DD);
        const float4* y4 = (const float4*)(Y + (size_t)warp * DD);
        float4 xv = x4[lane];
        float4 yv = y4[lane];
        {
            __nv_bfloat162 a = __float22bfloat162_rn(make_float2(xv.x, xv.y));
            __nv_bfloat162 b = __float22bfloat162_rn(make_float2(xv.z, xv.w));
            *(uint2*)(&g_Xb[(size_t)warp * DD + lane * 4]) =
                make_uint2(*(unsigned*)&a, *(unsigned*)&b);
            __nv_bfloat162 c = __float22bfloat162_rn(make_float2(yv.x, yv.y));
            __nv_bfloat162 d = __float22bfloat162_rn(make_float2(yv.z, yv.w));
            *(uint2*)(&g_Yb[(size_t)warp * DD + lane * 4]) =
                make_uint2(*(unsigned*)&c, *(unsigned*)&d);
        }
        float xn = xv.x * xv.x + xv.y * xv.y + xv.z * xv.z + xv.w * xv.w;
        float yn = yv.x * yv.x + yv.y * yv.y + yv.z * yv.z + yv.w * yv.w;
        float cr = xv.x * yv.x + xv.y * yv.y + xv.z * yv.z + xv.w * yv.w;
        for (int o = 16; o > 0; o >>= 1) {
            xn += __shfl_xor_sync(0xffffffffu, xn, o);
            yn += __shfl_xor_sync(0xffffffffu, yn, o);
            cr += __shfl_xor_sync(0xffffffffu, cr, o);
        }
        if (lane == 0) {
            float sq = fmaxf(yn + xn - 2.f * cr, 0.f);
            float p  = 1.f / (1.f + sq);
            float P  = -__logf(1.f + sq);
            g_p[warp]  = p;
            g_P[warp]  = P;
            g_yn[warp] = yn;
            g_xn[warp] = xn;
            int w = threadIdx.x >> 5;
            s_p[w] = (double)p;
            s_P[w] = (double)P;
        }
    }
    __syncthreads();
    if (threadIdx.x == 0) {
        double sp = 0.0, sP = 0.0;
        for (int w = 0; w < 8; w++) { sp += s_p[w]; sP += s_P[w]; }
        atomicAdd(&g_acc[0], sp);
        atomicAdd(&g_acc[1], sP);
    }
}

// ---------------------------------------------------------------- HMMA GEMM + epilogue
// 128x128 tile per CTA; 16 warps as 4x4 (32x32 each); mma.sync m16n8k16 bf16
// Full K=128 resident in smem [128][136] (pad 8 -> conflict-free frag loads)
#define LDK 136
#define SMEM_DYN (2 * TILE * LDK * 2)     // 69632 B: A | B (bf16); A reused as E stage
__global__ __launch_bounds__(512, 2)
void kGemm() {
    extern __shared__ __align__(16) char sm[];
    __shared__ float ys[TILE], xs[TILE], ps[TILE];
    __shared__ float red[3][16];

    __nv_bfloat16* smA = (__nv_bfloat16*)sm;                    // [128][136]
    __nv_bfloat16* smB = (__nv_bfloat16*)(sm + TILE * LDK * 2); // [128][136]
    __nv_bfloat16* smE = (__nv_bfloat16*)sm;                    // staging (reuse A)

    const int t    = threadIdx.x;
    const int wid  = t >> 5;
    const int lane = t & 31;
    const int g    = lane >> 2;
    const int t4   = lane & 3;
    const int wm   = wid >> 2;       // 0..3 -> 32-row band
    const int wn   = wid & 3;        // 0..3 -> 32-col band
    const int m0 = blockIdx.y * TILE;
    const int n0 = blockIdx.x * TILE;

    if (t < 128)      { ys[t] = g_yn[m0 + t]; ps[t] = g_p[m0 + t]; }
    else if (t < 256) { xs[t - 128] = g_xn[n0 + (t - 128)]; }

    // single load phase: full 128x128 bf16 A and B tiles
    for (int i = t; i < 2048; i += 512) {
        int row = i >> 4;
        int c8  = (i & 15) * 8;
        *(uint4*)&smA[row * LDK + c8] =
            *(const uint4*)&g_Yb[(size_t)(m0 + row) * DD + c8];
        *(uint4*)&smB[row * LDK + c8] =
            *(const uint4*)&g_Xb[(size_t)(n0 + row) * DD + c8];
    }
    __syncthreads();

    float acc[2][4][4];
#pragma unroll
    for (int m = 0; m < 2; m++)
#pragma unroll
        for (int n = 0; n < 4; n++)
#pragma unroll
            for (int r = 0; r < 4; r++) acc[m][n][r] = 0.f;

#pragma unroll
    for (int ks = 0; ks < 8; ks++) {
        const int kb = ks * 16;
        uint32_t bb[4][2];
#pragma unroll
        for (int n = 0; n < 4; n++) {
            int br = wn * 32 + n * 8 + g;
            bb[n][0] = *(const uint32_t*)&smB[br * LDK + kb + 2 * t4];
            bb[n][1] = *(const uint32_t*)&smB[br * LDK + kb + 8 + 2 * t4];
        }
#pragma unroll
        for (int m = 0; m < 2; m++) {
            int ar = wm * 32 + m * 16 + g;
            uint32_t a0 = *(const uint32_t*)&smA[ar * LDK + kb + 2 * t4];
            uint32_t a1 = *(const uint32_t*)&smA[(ar + 8) * LDK + kb + 2 * t4];
            uint32_t a2 = *(const uint32_t*)&smA[ar * LDK + kb + 8 + 2 * t4];
            uint32_t a3 = *(const uint32_t*)&smA[(ar + 8) * LDK + kb + 8 + 2 * t4];
#pragma unroll
            for (int n = 0; n < 4; n++) {
                asm volatile(
                    "mma.sync.aligned.m16n8k16.row.col.f32.bf16.bf16.f32 "
                    "{%0,%1,%2,%3}, {%4,%5,%6,%7}, {%8,%9}, {%0,%1,%2,%3};"
                    : "+f"(acc[m][n][0]), "+f"(acc[m][n][1]),
                      "+f"(acc[m][n][2]), "+f"(acc[m][n][3])
                    : "r"(a0), "r"(a1), "r"(a2), "r"(a3),
                      "r"(bb[n][0]), "r"(bb[n][1]));
            }
        }
    }
    __syncthreads();   // A/B no longer needed; smE staging may overwrite

    // ------- epilogue: e = 1/(1+sq), stats, stage bf16 e in smem -------
    // logs fused over 8 elems: log(prod) — fp32-range safe (op<=~600, h>=~1e-3)
    float se = 0.f, slE = 0.f, slM = 0.f;
#pragma unroll
    for (int m = 0; m < 2; m++) {
#pragma unroll
        for (int rr = 0; rr < 2; rr++) {
            const int rloc = wm * 32 + m * 16 + rr * 8 + g;
            const float yni = ys[rloc];
            const float pmi = ps[rloc];
            float er = 0.f, prE = 1.f, prM = 1.f;
#pragma unroll
            for (int n = 0; n < 4; n++) {
                const int cloc = wn * 32 + n * 8 + 2 * t4;
                float d0 = acc[m][n][rr * 2 + 0];
                float d1 = acc[m][n][rr * 2 + 1];
                float sq0 = fmaxf(yni + xs[cloc]     - 2.f * d0, 0.f);
                float sq1 = fmaxf(yni + xs[cloc + 1] - 2.f * d1, 0.f);
                float op0 = 1.f + sq0, op1 = 1.f + sq1;
                float e0 = __fdividef(1.f, op0);
                float e1 = __fdividef(1.f, op1);
                se  += e0 + e1;
                er  += e0 + e1;
                prE *= op0 * op1;
                prM *= (0.5f * (pmi + e0)) * (0.5f * (pmi + e1));
                __nv_bfloat162 pb = __float22bfloat162_rn(make_float2(e0, e1));
                *(uint32_t*)&smE[rloc * LDK + cloc] = *(unsigned*)&pb;
            }
            slE -= __logf(prE);
            slM += __logf(prM);
            // reduce row sum over the 4 lanes sharing this row (t4 group)
            er += __shfl_xor_sync(0xffffffffu, er, 1);
            er += __shfl_xor_sync(0xffffffffu, er, 2);
            if (t4 == 0) atomicAdd(&g_Row[m0 + rloc], er);
        }
    }

    // block reduce the 3 scalars
    for (int o = 16; o > 0; o >>= 1) {
        se  += __shfl_xor_sync(0xffffffffu, se, o);
        slE += __shfl_xor_sync(0xffffffffu, slE, o);
        slM += __shfl_xor_sync(0xffffffffu, slM, o);
    }
    if (lane == 0) { red[0][wid] = se; red[1][wid] = slE; red[2][wid] = slM; }
    __syncthreads();   // also orders smE writes before the cooperative store
    if (t == 0) {
        double a0 = 0, a1 = 0, a2 = 0;
        for (int k = 0; k < 16; k++) { a0 += red[0][k]; a1 += red[1][k]; a2 += red[2][k]; }
        atomicAdd(&g_acc[2], a0);
        atomicAdd(&g_acc[3], a1);
        atomicAdd(&g_acc[4], a2);
    }

    // coalesced store of staged e tile: 128 rows x 16 chunks of 8 bf16 (uint4)
    for (int i = t; i < 2048; i += 512) {
        int row = i >> 4;
        int c8  = (i & 15) * 8;
        *(uint4*)&g_E[(size_t)(m0 + row) * NN + n0 + c8] =
            *(const uint4*)&smE[row * LDK + c8];
    }
}

// ---------------------------------------------------------------- sigmoid pass
#define SIG_BLOCKS 1184
__global__ __launch_bounds__(256, 8) void kSig() {
    double Sp    = g_acc[0];
    double S_all = g_acc[2];
    double S_N   = S_all - Sp;
    double S_M   = 0.5 * ((double)(NN - 1) * Sp + S_N);
    const double cnt = (double)NN * (double)(NN - 1);
    float C = (float)((S_M / cnt) * (S_N / cnt));

    const size_t nvec   = (size_t)NN * NN / 8;
    const size_t stride = (size_t)SIG_BLOCKS * 256;
    size_t tid = (size_t)blockIdx.x * 256 + threadIdx.x;

    float sp = 0.f, sn = 0.f;
    for (size_t i = tid; i < nvec; i += stride) {
        int m = (int)((i * 8) >> 12);
        float pm = __ldg(&g_p[m]);
        uint4 raw = __ldg((const uint4*)&g_E[i * 8]);
        float2 f;
        float e;
#define SIG_TERM(E) { e = (E); float u = 0.5f * pm * (pm + e), v = 0.5f * (pm + e) * e; \
                      sp += __fdividef(u, u + C); sn += __fdividef(v, v + C); }
        f = __bfloat1622float2(*(__nv_bfloat162*)&raw.x); SIG_TERM(f.x); SIG_TERM(f.y);
        f = __bfloat1622float2(*(__nv_bfloat162*)&raw.y); SIG_TERM(f.x); SIG_TERM(f.y);
        f = __bfloat1622float2(*(__nv_bfloat162*)&raw.z); SIG_TERM(f.x); SIG_TERM(f.y);
        f = __bfloat1622float2(*(__nv_bfloat162*)&raw.w); SIG_TERM(f.x); SIG_TERM(f.y);
#undef SIG_TERM
    }
    for (int o = 16; o > 0; o >>= 1) {
        sp += __shfl_xor_sync(0xffffffffu, sp, o);
        sn += __shfl_xor_sync(0xffffffffu, sn, o);
    }
    __shared__ double rp[8], rn_[8];
    int w = threadIdx.x >> 5;
    if ((threadIdx.x & 31) == 0) { rp[w] = (double)sp; rn_[w] = (double)sn; }
    __syncthreads();
    if (threadIdx.x == 0) {
        double a = 0, b = 0;
        for (int k = 0; k < 8; k++) { a += rp[k]; b += rn_[k]; }
        atomicAdd(&g_acc[5], a);
        atomicAdd(&g_acc[6], b);
    }
}

// ---------------------------------------------------------------- final (+ state reset)
__global__ void kFinal(float* __restrict__ out) {
    __shared__ double s_tp[256], s_d[256];
    int t = threadIdx.x;
    double Sp = g_acc[0], SP = g_acc[1], S_all = g_acc[2];
    double SlogE = g_acc[3], SlogM = g_acc[4], SsP = g_acc[5], SsN = g_acc[6];
    double S_N = S_all - Sp;
    const double cnt = (double)NN * (double)(NN - 1);
    double S_M = 0.5 * ((NN - 1.0) * Sp + S_N);
    double C   = (S_M / cnt) * (S_N / cnt);

    double tp = 0.0, dd = 0.0;
    for (int i = t; i < NN; i += 256) {
        double pm = (double)g_p[i];
        double R  = (double)g_Row[i] - pm;
        double w  = pm * 0.5 * ((NN - 1.0) * pm + R) / (NN - 1.0);
        tp += w / (w + C);
        dd += pm * pm / (pm * pm + C);
    }
    s_tp[t] = tp; s_d[t] = dd;
    __syncthreads();
    for (int o = 128; o > 0; o >>= 1) {
        if (t < o) { s_tp[t] += s_tp[t + o]; s_d[t] += s_d[t + o]; }
        __syncthreads();
    }
    if (t == 0) {
        double TP   = s_tp[0] / NN;
        double dsum = s_d[0];
        double lb0 = log(S_M / cnt), lb1 = log(S_N / cnt), L = lb0 + lb1;
        double meanP = SP / NN;
        double meanM = (SlogM - SP) / cnt;
        double meanN = (SlogE - SP) / cnt;
        double o0 = meanP + meanM - L;
        double o1 = meanM + meanN - L;
        double sigP = (SsP - dsum) / cnt;
        double sigN = (SsN - dsum) / cnt;
        double FP = sigN;
        out[0] = (float)o0;
        out[1] = (float)o1;
        out[2] = (float)sigP;
        out[3] = (float)sigN;
        out[4] = (float)((TP + 1.0 - FP) * 0.5);
        out[5] = (float)TP;
        out[6] = (float)(TP / (TP + FP));
        out[7] = (float)L;
        out[8] = (float)(2.0 - o0);
    }
    // reset accumulators for the next (replayed) run — all reads above are done
    for (int i = t; i < NN; i += 256) g_Row[i] = 0.f;
    if (t < 8) g_acc[t] = 0.0;
}

// ---------------------------------------------------------------- launch
extern "C" void kernel_launch(void* const* d_in, const int* in_sizes, int n_in,
                              void* d_out, int out_size) {
    const float* X = (const float*)d_in[0];   // z_x  (columns j)
    const float* Y = (const float*)d_in[1];   // z_y  (rows i)
    cudaFuncSetAttribute(kGemm, cudaFuncAttributeMaxDynamicSharedMemorySize, SMEM_DYN);
    kDiag<<<NN / 8, 256>>>(X, Y);
    kGemm<<<dim3(NN / TILE, NN / TILE), 512, SMEM_DYN>>>();
    kSig<<<SIG_BLOCKS, 256>>>();
    kFinal<<<1, 256>>>((float*)d_out);
}

// round 13
// speedup vs baseline: 2.8736x; 1.5676x over previous
#include <cuda_runtime.h>
#include <cuda_bf16.h>
#include <cstdint>

#define NN 4096
#define DD 128
#define TILE 128

// ---------------------------------------------------------------- scratch
__device__ __nv_bfloat16 g_E[(size_t)NN * NN];           // 32 MB e_ij
__device__ __nv_bfloat16 g_Xb[(size_t)NN * DD];          // bf16 copies of inputs
__device__ __nv_bfloat16 g_Yb[(size_t)NN * DD];
__device__ float  g_p[NN], g_P[NN], g_yn[NN], g_xn[NN], g_Row[NN];
__device__ double g_acc[10];
// g_acc: [0]=Sp [1]=SP [2]=S_all [3]=SlogE [4]=SlogM [5]=SsigPos [6]=SsigNeg
//        [7]=Stp (row sigmoid-pos) [8]=Sdd (diag sigmoid correction)
// NOTE: g_acc and g_Row are zero at module load and re-zeroed at the END of
// kFinal each run, so every replay starts clean (graph-deterministic).

// ---------------------------------------------------------------- diag + norms + bf16 convert
__global__ void kDiag(const float* __restrict__ X, const float* __restrict__ Y) {
    int warp = (blockIdx.x * blockDim.x + threadIdx.x) >> 5;
    int lane = threadIdx.x & 31;
    __shared__ double s_p[8], s_P[8];
    if (warp < NN) {
        const float4* x4 = (const float4*)(X + (size_t)warp * DD);
        const float4* y4 = (const float4*)(Y + (size_t)warp * DD);
        float4 xv = x4[lane];
        float4 yv = y4[lane];
        {
            __nv_bfloat162 a = __float22bfloat162_rn(make_float2(xv.x, xv.y));
            __nv_bfloat162 b = __float22bfloat162_rn(make_float2(xv.z, xv.w));
            *(uint2*)(&g_Xb[(size_t)warp * DD + lane * 4]) =
                make_uint2(*(unsigned*)&a, *(unsigned*)&b);
            __nv_bfloat162 c = __float22bfloat162_rn(make_float2(yv.x, yv.y));
            __nv_bfloat162 d = __float22bfloat162_rn(make_float2(yv.z, yv.w));
            *(uint2*)(&g_Yb[(size_t)warp * DD + lane * 4]) =
                make_uint2(*(unsigned*)&c, *(unsigned*)&d);
        }
        float xn = xv.x * xv.x + xv.y * xv.y + xv.z * xv.z + xv.w * xv.w;
        float yn = yv.x * yv.x + yv.y * yv.y + yv.z * yv.z + yv.w * yv.w;
        float cr = xv.x * yv.x + xv.y * yv.y + xv.z * yv.z + xv.w * yv.w;
        for (int o = 16; o > 0; o >>= 1) {
            xn += __shfl_xor_sync(0xffffffffu, xn, o);
            yn += __shfl_xor_sync(0xffffffffu, yn, o);
            cr += __shfl_xor_sync(0xffffffffu, cr, o);
        }
        if (lane == 0) {
            float sq = fmaxf(yn + xn - 2.f * cr, 0.f);
            float p  = 1.f / (1.f + sq);
            float P  = -__logf(1.f + sq);
            g_p[warp]  = p;
            g_P[warp]  = P;
            g_yn[warp] = yn;
            g_xn[warp] = xn;
            int w = threadIdx.x >> 5;
            s_p[w] = (double)p;
            s_P[w] = (double)P;
        }
    }
    __syncthreads();
    if (threadIdx.x == 0) {
        double sp = 0.0, sP = 0.0;
        for (int w = 0; w < 8; w++) { sp += s_p[w]; sP += s_P[w]; }
        atomicAdd(&g_acc[0], sp);
        atomicAdd(&g_acc[1], sP);
    }
}

// ---------------------------------------------------------------- HMMA GEMM + epilogue
// 128x128 tile per CTA; 16 warps as 4x4 (32x32 each); mma.sync m16n8k16 bf16
// Full K=128 resident in smem [128][136] (pad 8 -> conflict-free frag loads)
#define LDK 136
#define SMEM_DYN (2 * TILE * LDK * 2)     // 69632 B: A | B (bf16); A reused as E stage
__global__ __launch_bounds__(512, 2)
void kGemm() {
    extern __shared__ __align__(16) char sm[];
    __shared__ float ys[TILE], xs[TILE], ps[TILE];
    __shared__ float red[3][16];

    __nv_bfloat16* smA = (__nv_bfloat16*)sm;                    // [128][136]
    __nv_bfloat16* smB = (__nv_bfloat16*)(sm + TILE * LDK * 2); // [128][136]
    __nv_bfloat16* smE = (__nv_bfloat16*)sm;                    // staging (reuse A)

    const int t    = threadIdx.x;
    const int wid  = t >> 5;
    const int lane = t & 31;
    const int g    = lane >> 2;
    const int t4   = lane & 3;
    const int wm   = wid >> 2;       // 0..3 -> 32-row band
    const int wn   = wid & 3;        // 0..3 -> 32-col band
    const int m0 = blockIdx.y * TILE;
    const int n0 = blockIdx.x * TILE;

    if (t < 128)      { ys[t] = g_yn[m0 + t]; ps[t] = g_p[m0 + t]; }
    else if (t < 256) { xs[t - 128] = g_xn[n0 + (t - 128)]; }

    // single load phase: full 128x128 bf16 A and B tiles
    for (int i = t; i < 2048; i += 512) {
        int row = i >> 4;
        int c8  = (i & 15) * 8;
        *(uint4*)&smA[row * LDK + c8] =
            *(const uint4*)&g_Yb[(size_t)(m0 + row) * DD + c8];
        *(uint4*)&smB[row * LDK + c8] =
            *(const uint4*)&g_Xb[(size_t)(n0 + row) * DD + c8];
    }
    __syncthreads();

    float acc[2][4][4];
#pragma unroll
    for (int m = 0; m < 2; m++)
#pragma unroll
        for (int n = 0; n < 4; n++)
#pragma unroll
            for (int r = 0; r < 4; r++) acc[m][n][r] = 0.f;

#pragma unroll
    for (int ks = 0; ks < 8; ks++) {
        const int kb = ks * 16;
        uint32_t bb[4][2];
#pragma unroll
        for (int n = 0; n < 4; n++) {
            int br = wn * 32 + n * 8 + g;
            bb[n][0] = *(const uint32_t*)&smB[br * LDK + kb + 2 * t4];
            bb[n][1] = *(const uint32_t*)&smB[br * LDK + kb + 8 + 2 * t4];
        }
#pragma unroll
        for (int m = 0; m < 2; m++) {
            int ar = wm * 32 + m * 16 + g;
            uint32_t a0 = *(const uint32_t*)&smA[ar * LDK + kb + 2 * t4];
            uint32_t a1 = *(const uint32_t*)&smA[(ar + 8) * LDK + kb + 2 * t4];
            uint32_t a2 = *(const uint32_t*)&smA[ar * LDK + kb + 8 + 2 * t4];
            uint32_t a3 = *(const uint32_t*)&smA[(ar + 8) * LDK + kb + 8 + 2 * t4];
#pragma unroll
            for (int n = 0; n < 4; n++) {
                asm volatile(
                    "mma.sync.aligned.m16n8k16.row.col.f32.bf16.bf16.f32 "
                    "{%0,%1,%2,%3}, {%4,%5,%6,%7}, {%8,%9}, {%0,%1,%2,%3};"
                    : "+f"(acc[m][n][0]), "+f"(acc[m][n][1]),
                      "+f"(acc[m][n][2]), "+f"(acc[m][n][3])
                    : "r"(a0), "r"(a1), "r"(a2), "r"(a3),
                      "r"(bb[n][0]), "r"(bb[n][1]));
            }
        }
    }
    __syncthreads();   // A/B no longer needed; smE staging may overwrite

    // ------- epilogue: e = 1/(1+sq), stats, stage bf16 e in smem -------
    // logs fused over 8 elems: log(prod) — fp32-range safe (op<=~600, h>=~1e-3)
    float se = 0.f, slE = 0.f, slM = 0.f;
#pragma unroll
    for (int m = 0; m < 2; m++) {
#pragma unroll
        for (int rr = 0; rr < 2; rr++) {
            const int rloc = wm * 32 + m * 16 + rr * 8 + g;
            const float yni = ys[rloc];
            const float pmi = ps[rloc];
            float er = 0.f, prE = 1.f, prM = 1.f;
#pragma unroll
            for (int n = 0; n < 4; n++) {
                const int cloc = wn * 32 + n * 8 + 2 * t4;
                float d0 = acc[m][n][rr * 2 + 0];
                float d1 = acc[m][n][rr * 2 + 1];
                float sq0 = fmaxf(yni + xs[cloc]     - 2.f * d0, 0.f);
                float sq1 = fmaxf(yni + xs[cloc + 1] - 2.f * d1, 0.f);
                float op0 = 1.f + sq0, op1 = 1.f + sq1;
                float e0 = __fdividef(1.f, op0);
                float e1 = __fdividef(1.f, op1);
                se  += e0 + e1;
                er  += e0 + e1;
                prE *= op0 * op1;
                prM *= (0.5f * (pmi + e0)) * (0.5f * (pmi + e1));
                __nv_bfloat162 pb = __float22bfloat162_rn(make_float2(e0, e1));
                *(uint32_t*)&smE[rloc * LDK + cloc] = *(unsigned*)&pb;
            }
            slE -= __logf(prE);
            slM += __logf(prM);
            // reduce row sum over the 4 lanes sharing this row (t4 group)
            er += __shfl_xor_sync(0xffffffffu, er, 1);
            er += __shfl_xor_sync(0xffffffffu, er, 2);
            if (t4 == 0) atomicAdd(&g_Row[m0 + rloc], er);
        }
    }

    // block reduce the 3 scalars
    for (int o = 16; o > 0; o >>= 1) {
        se  += __shfl_xor_sync(0xffffffffu, se, o);
        slE += __shfl_xor_sync(0xffffffffu, slE, o);
        slM += __shfl_xor_sync(0xffffffffu, slM, o);
    }
    if (lane == 0) { red[0][wid] = se; red[1][wid] = slE; red[2][wid] = slM; }
    __syncthreads();   // also orders smE writes before the cooperative store
    if (t == 0) {
        double a0 = 0, a1 = 0, a2 = 0;
        for (int k = 0; k < 16; k++) { a0 += red[0][k]; a1 += red[1][k]; a2 += red[2][k]; }
        atomicAdd(&g_acc[2], a0);
        atomicAdd(&g_acc[3], a1);
        atomicAdd(&g_acc[4], a2);
    }

    // coalesced store of staged e tile: 128 rows x 16 chunks of 8 bf16 (uint4)
    for (int i = t; i < 2048; i += 512) {
        int row = i >> 4;
        int c8  = (i & 15) * 8;
        *(uint4*)&g_E[(size_t)(m0 + row) * NN + n0 + c8] =
            *(const uint4*)&smE[row * LDK + c8];
    }
}

// ---------------------------------------------------------------- per-row sigmoid terms
// one thread per row; fp32 values (O(1)), double accumulation
__global__ void kRows() {
    double Sp    = g_acc[0];
    double S_all = g_acc[2];
    double S_N   = S_all - Sp;
    double S_M   = 0.5 * ((double)(NN - 1) * Sp + S_N);
    const double cnt = (double)NN * (double)(NN - 1);
    float C = (float)((S_M / cnt) * (S_N / cnt));

    int i = blockIdx.x * 256 + threadIdx.x;
    float pm = g_p[i];
    float R  = g_Row[i] - pm;                         // off-diagonal row sum
    float w  = pm * 0.5f * ((NN - 1.f) * pm + R) * (1.f / (NN - 1.f));
    float tp = __fdividef(w, w + C);
    float dd = __fdividef(pm * pm, pm * pm + C);
    for (int o = 16; o > 0; o >>= 1) {
        tp += __shfl_xor_sync(0xffffffffu, tp, o);
        dd += __shfl_xor_sync(0xffffffffu, dd, o);
    }
    __shared__ double s_t[8], s_d[8];
    int wd = threadIdx.x >> 5;
    if ((threadIdx.x & 31) == 0) { s_t[wd] = (double)tp; s_d[wd] = (double)dd; }
    __syncthreads();
    if (threadIdx.x == 0) {
        double a = 0, b = 0;
        for (int k = 0; k < 8; k++) { a += s_t[k]; b += s_d[k]; }
        atomicAdd(&g_acc[7], a);
        atomicAdd(&g_acc[8], b);
    }
}

// ---------------------------------------------------------------- sigmoid pass
#define SIG_BLOCKS 1184
__global__ __launch_bounds__(256, 8) void kSig() {
    double Sp    = g_acc[0];
    double S_all = g_acc[2];
    double S_N   = S_all - Sp;
    double S_M   = 0.5 * ((double)(NN - 1) * Sp + S_N);
    const double cnt = (double)NN * (double)(NN - 1);
    float C = (float)((S_M / cnt) * (S_N / cnt));

    const size_t nvec   = (size_t)NN * NN / 8;
    const size_t stride = (size_t)SIG_BLOCKS * 256;
    size_t tid = (size_t)blockIdx.x * 256 + threadIdx.x;

    float sp = 0.f, sn = 0.f;
    for (size_t i = tid; i < nvec; i += stride) {
        int m = (int)((i * 8) >> 12);
        float pm = __ldg(&g_p[m]);
        uint4 raw = __ldg((const uint4*)&g_E[i * 8]);
        float2 f;
        float e;
#define SIG_TERM(E) { e = (E); float u = 0.5f * pm * (pm + e), v = 0.5f * (pm + e) * e; \
                      sp += __fdividef(u, u + C); sn += __fdividef(v, v + C); }
        f = __bfloat1622float2(*(__nv_bfloat162*)&raw.x); SIG_TERM(f.x); SIG_TERM(f.y);
        f = __bfloat1622float2(*(__nv_bfloat162*)&raw.y); SIG_TERM(f.x); SIG_TERM(f.y);
        f = __bfloat1622float2(*(__nv_bfloat162*)&raw.z); SIG_TERM(f.x); SIG_TERM(f.y);
        f = __bfloat1622float2(*(__nv_bfloat162*)&raw.w); SIG_TERM(f.x); SIG_TERM(f.y);
#undef SIG_TERM
    }
    for (int o = 16; o > 0; o >>= 1) {
        sp += __shfl_xor_sync(0xffffffffu, sp, o);
        sn += __shfl_xor_sync(0xffffffffu, sn, o);
    }
    __shared__ double rp[8], rn_[8];
    int w = threadIdx.x >> 5;
    if ((threadIdx.x & 31) == 0) { rp[w] = (double)sp; rn_[w] = (double)sn; }
    __syncthreads();
    if (threadIdx.x == 0) {
        double a = 0, b = 0;
        for (int k = 0; k < 8; k++) { a += rp[k]; b += rn_[k]; }
        atomicAdd(&g_acc[5], a);
        atomicAdd(&g_acc[6], b);
    }
}

// ---------------------------------------------------------------- final (+ state reset)
// scalar-only: double multiplies (no double division), fp32 logs/divides
__global__ void kFinal(float* __restrict__ out) {
    int t = threadIdx.x;
    if (t == 0) {
        const double inv_cnt = 1.0 / ((double)NN * (double)(NN - 1));
        const double inv_nn  = 1.0 / (double)NN;
        double Sp = g_acc[0], SP = g_acc[1], S_all = g_acc[2];
        double SlogE = g_acc[3], SlogM = g_acc[4], SsP = g_acc[5], SsN = g_acc[6];
        double Stp = g_acc[7], Sdd = g_acc[8];
        double S_N = S_all - Sp;
        double S_M = 0.5 * ((NN - 1.0) * Sp + S_N);

        float mM = (float)(S_M * inv_cnt);
        float mN = (float)(S_N * inv_cnt);
        float L  = __logf(mM) + __logf(mN);

        double meanP = SP * inv_nn;
        double meanM = (SlogM - SP) * inv_cnt;
        double meanN = (SlogE - SP) * inv_cnt;
        float o0 = (float)(meanP + meanM) - L;
        float o1 = (float)(meanM + meanN) - L;

        float TP   = (float)(Stp * inv_nn);
        float sigP = (float)((SsP - Sdd) * inv_cnt);
        float sigN = (float)((SsN - Sdd) * inv_cnt);
        float FP = sigN;
        out[0] = o0;
        out[1] = o1;
        out[2] = sigP;
        out[3] = sigN;
        out[4] = (TP + 1.f - FP) * 0.5f;
        out[5] = TP;
        out[6] = __fdividef(TP, TP + FP);
        out[7] = L;
        out[8] = 2.f - o0;
    }
    // reset accumulators for the next (replayed) run
    for (int i = t; i < NN; i += 256) g_Row[i] = 0.f;
    __syncthreads();
    if (t < 10) g_acc[t] = 0.0;
}

// ---------------------------------------------------------------- launch
extern "C" void kernel_launch(void* const* d_in, const int* in_sizes, int n_in,
                              void* d_out, int out_size) {
    const float* X = (const float*)d_in[0];   // z_x  (columns j)
    const float* Y = (const float*)d_in[1];   // z_y  (rows i)
    cudaFuncSetAttribute(kGemm, cudaFuncAttributeMaxDynamicSharedMemorySize, SMEM_DYN);
    kDiag<<<NN / 8, 256>>>(X, Y);
    kGemm<<<dim3(NN / TILE, NN / TILE), 512, SMEM_DYN>>>();
    kRows<<<NN / 256, 256>>>();
    kSig<<<SIG_BLOCKS, 256>>>();
    kFinal<<<1, 256>>>((float*)d_out);
}